// round 1
// baseline (speedup 1.0000x reference)
#include <cuda_runtime.h>
#include <cuda_bf16.h>
#include <math_constants.h>

#define N_NODES 100000
#define N_EDGES 1600000
#define IN_DIM 256
#define HEADS 4
#define OUT_DIM 32
#define FEAT_DIM 128   // HEADS * OUT_DIM
#define NEG_SLOPE 0.2f

#define SCAN_B 1024
#define NB ((N_NODES + SCAN_B - 1) / SCAN_B)   // 98

// ---------------- scratch (static device globals; no runtime alloc) --------
__device__ float g_feat[(size_t)N_NODES * FEAT_DIM];   // 51.2 MB
__device__ float g_el[N_NODES * HEADS];
__device__ float g_er[N_NODES * HEADS];
__device__ int   g_deg[N_NODES];
__device__ int   g_off[N_NODES + 1];
__device__ int   g_cur[N_NODES];
__device__ int   g_eidx[N_EDGES];
__device__ int   g_bsums[128];

// ---------------- f32x2 packed helpers (FFMA2 path, 2x fp32 throughput) ----
__device__ __forceinline__ unsigned long long pack2(float a, float b) {
    unsigned long long r;
    asm("mov.b64 %0, {%1, %2};" : "=l"(r) : "f"(a), "f"(b));
    return r;
}
__device__ __forceinline__ unsigned long long fma2(unsigned long long a,
                                                   unsigned long long b,
                                                   unsigned long long c) {
    unsigned long long d;
    asm("fma.rn.f32x2 %0, %1, %2, %3;" : "=l"(d) : "l"(a), "l"(b), "l"(c));
    return d;
}
__device__ __forceinline__ float2 unpack2(unsigned long long v) {
    float2 r;
    asm("mov.b64 {%0, %1}, %2;" : "=f"(r.x), "=f"(r.y) : "l"(v));
    return r;
}

// ---------------- GEMM: feat = x @ W  (M x 256 @ 256 x 128) ----------------
#define BM 128
#define BN 128
#define BK 16

__global__ __launch_bounds__(256) void gemm_kernel(const float* __restrict__ A,
                                                   const float* __restrict__ B) {
    __shared__ float As[BK][BM];
    __shared__ float Bs[BK][BN];
    const int tid = threadIdx.x;
    const int block_row = blockIdx.x * BM;
    const int ty = tid >> 4;   // 0..15
    const int tx = tid & 15;   // 0..15

    // acc[i][j] packs (C[2i][j], C[2i+1][j]) for this thread's 8x8 microtile
    unsigned long long acc[4][8];
#pragma unroll
    for (int i = 0; i < 4; i++)
#pragma unroll
        for (int j = 0; j < 8; j++) acc[i][j] = 0ULL;

    for (int kk = 0; kk < IN_DIM; kk += BK) {
        // A tile: 128 rows x 16 k, transpose into As[k][m]
#pragma unroll
        for (int it = 0; it < 2; it++) {
            int t  = tid + it * 256;
            int m  = t >> 2;
            int k4 = (t & 3) << 2;
            int row = block_row + m;
            int rc  = row < N_NODES ? row : N_NODES - 1;
            float4 v = *(const float4*)(A + (size_t)rc * IN_DIM + kk + k4);
            if (row >= N_NODES) v = make_float4(0.f, 0.f, 0.f, 0.f);
            As[k4 + 0][m] = v.x; As[k4 + 1][m] = v.y;
            As[k4 + 2][m] = v.z; As[k4 + 3][m] = v.w;
        }
        // B tile: 16 x 128 direct
#pragma unroll
        for (int it = 0; it < 2; it++) {
            int t = tid + it * 256;
            int r = t >> 5;
            int c = (t & 31) << 2;
            *(float4*)&Bs[r][c] = *(const float4*)(B + (size_t)(kk + r) * FEAT_DIM + c);
        }
        __syncthreads();
#pragma unroll
        for (int k = 0; k < BK; k++) {
            const unsigned long long* a2 =
                (const unsigned long long*)&As[k][ty << 3];
            unsigned long long av[4];
            av[0] = a2[0]; av[1] = a2[1]; av[2] = a2[2]; av[3] = a2[3];
            float4 b0 = *(const float4*)&Bs[k][tx << 3];
            float4 b1 = *(const float4*)&Bs[k][(tx << 3) + 4];
            unsigned long long bb[8];
            bb[0] = pack2(b0.x, b0.x); bb[1] = pack2(b0.y, b0.y);
            bb[2] = pack2(b0.z, b0.z); bb[3] = pack2(b0.w, b0.w);
            bb[4] = pack2(b1.x, b1.x); bb[5] = pack2(b1.y, b1.y);
            bb[6] = pack2(b1.z, b1.z); bb[7] = pack2(b1.w, b1.w);
#pragma unroll
            for (int i = 0; i < 4; i++)
#pragma unroll
                for (int j = 0; j < 8; j++)
                    acc[i][j] = fma2(av[i], bb[j], acc[i][j]);
        }
        __syncthreads();
    }

    // epilogue: unpack and store
#pragma unroll
    for (int i = 0; i < 4; i++) {
        float lo[8], hi[8];
#pragma unroll
        for (int j = 0; j < 8; j++) {
            float2 p = unpack2(acc[i][j]);
            lo[j] = p.x; hi[j] = p.y;
        }
        int r0 = block_row + (ty << 3) + 2 * i;
        if (r0 < N_NODES) {
            *(float4*)&g_feat[(size_t)r0 * FEAT_DIM + (tx << 3)] =
                make_float4(lo[0], lo[1], lo[2], lo[3]);
            *(float4*)&g_feat[(size_t)r0 * FEAT_DIM + (tx << 3) + 4] =
                make_float4(lo[4], lo[5], lo[6], lo[7]);
        }
        if (r0 + 1 < N_NODES) {
            *(float4*)&g_feat[(size_t)(r0 + 1) * FEAT_DIM + (tx << 3)] =
                make_float4(hi[0], hi[1], hi[2], hi[3]);
            *(float4*)&g_feat[(size_t)(r0 + 1) * FEAT_DIM + (tx << 3) + 4] =
                make_float4(hi[4], hi[5], hi[6], hi[7]);
        }
    }
}

// ---------------- el/er: per-(node,head) attention dot ---------------------
__global__ __launch_bounds__(256) void elr_kernel(const float* __restrict__ attn_l,
                                                  const float* __restrict__ attn_r) {
    int warp = (blockIdx.x * blockDim.x + threadIdx.x) >> 5;
    int lane = threadIdx.x & 31;
    if (warp >= N_NODES) return;
    int h = lane >> 3;
    int q = lane & 7;
    float4 f  = *(const float4*)&g_feat[(size_t)warp * FEAT_DIM + lane * 4];
    float4 al = *(const float4*)&attn_l[h * OUT_DIM + q * 4];
    float4 ar = *(const float4*)&attn_r[h * OUT_DIM + q * 4];
    float sl = f.x * al.x + f.y * al.y + f.z * al.z + f.w * al.w;
    float sr = f.x * ar.x + f.y * ar.y + f.z * ar.z + f.w * ar.w;
#pragma unroll
    for (int o = 4; o >= 1; o >>= 1) {
        sl += __shfl_xor_sync(0xffffffffu, sl, o);
        sr += __shfl_xor_sync(0xffffffffu, sr, o);
    }
    if (q == 0) {
        g_el[warp * HEADS + h] = sl;
        g_er[warp * HEADS + h] = sr;
    }
}

// ---------------- CSR build ------------------------------------------------
__global__ void zero_deg_kernel() {
    int i = blockIdx.x * blockDim.x + threadIdx.x;
    if (i < N_NODES) g_deg[i] = 0;
}

__global__ void hist_kernel(const int* __restrict__ dst) {
    int i = blockIdx.x * blockDim.x + threadIdx.x;
    if (i < N_EDGES) atomicAdd(&g_deg[dst[i]], 1);
}

__global__ __launch_bounds__(SCAN_B) void scan1_kernel() {
    __shared__ int wsum[32];
    int i = blockIdx.x * SCAN_B + threadIdx.x;
    int lane = threadIdx.x & 31;
    int wid  = threadIdx.x >> 5;
    int v = (i < N_NODES) ? g_deg[i] : 0;
    int x = v;
#pragma unroll
    for (int o = 1; o < 32; o <<= 1) {
        int y = __shfl_up_sync(0xffffffffu, x, o);
        if (lane >= o) x += y;
    }
    if (lane == 31) wsum[wid] = x;
    __syncthreads();
    if (threadIdx.x < 32) {
        int w = wsum[threadIdx.x];
#pragma unroll
        for (int o = 1; o < 32; o <<= 1) {
            int y = __shfl_up_sync(0xffffffffu, w, o);
            if ((int)threadIdx.x >= o) w += y;
        }
        wsum[threadIdx.x] = w;
    }
    __syncthreads();
    int base = wid ? wsum[wid - 1] : 0;
    int incl = x + base;
    if (i < N_NODES) g_off[i] = incl;          // temp: block-inclusive
    if (threadIdx.x == SCAN_B - 1) g_bsums[blockIdx.x] = incl;
}

__global__ void scan2_kernel() {
    __shared__ int ws[4];
    int t = threadIdx.x;          // 128 threads
    int lane = t & 31;
    int wid  = t >> 5;
    int v = (t < NB) ? g_bsums[t] : 0;
    int x = v;
#pragma unroll
    for (int o = 1; o < 32; o <<= 1) {
        int y = __shfl_up_sync(0xffffffffu, x, o);
        if (lane >= o) x += y;
    }
    if (lane == 31) ws[wid] = x;
    __syncthreads();
    int base = 0;
    for (int w = 0; w < wid; w++) base += ws[w];
    g_bsums[t] = x + base;        // global inclusive
}

__global__ void scan3_kernel() {
    int i = blockIdx.x * blockDim.x + threadIdx.x;
    if (i < N_NODES) {
        int b = i >> 10;
        int add = b ? g_bsums[b - 1] : 0;
        int incl = g_off[i] + add;
        int excl = incl - g_deg[i];
        g_off[i] = excl;
        g_cur[i] = excl;
        if (i == 0) g_off[N_NODES] = g_bsums[NB - 1];
    }
}

__global__ void scatter_kernel(const int* __restrict__ dst) {
    int i = blockIdx.x * blockDim.x + threadIdx.x;
    if (i < N_EDGES) {
        int p = atomicAdd(&g_cur[dst[i]], 1);
        g_eidx[p] = i;
    }
}

// ---------------- fused softmax + aggregation: one warp per dst node -------
__global__ __launch_bounds__(256) void aggregate_kernel(const int* __restrict__ src,
                                                        float* __restrict__ out) {
    int n    = (blockIdx.x * blockDim.x + threadIdx.x) >> 5;
    int lane = threadIdx.x & 31;
    if (n >= N_NODES) return;
    int h = lane >> 3;   // head for this lane
    int q = lane & 7;    // quad within head

    int begin = g_off[n];
    int end   = g_off[n + 1];
    float4 er4 = *(const float4*)&g_er[n * HEADS];

    // ---- pass 1: per-head max over incoming edges (lanes split edges) ----
    float4 mx = make_float4(-CUDART_INF_F, -CUDART_INF_F, -CUDART_INF_F, -CUDART_INF_F);
    for (int i = begin + lane; i < end; i += 32) {
        int e = g_eidx[i];
        int s = src[e];
        float4 el4 = *(const float4*)&g_el[s * HEADS];
        float e0 = el4.x + er4.x; e0 = e0 > 0.f ? e0 : NEG_SLOPE * e0;
        float e1 = el4.y + er4.y; e1 = e1 > 0.f ? e1 : NEG_SLOPE * e1;
        float e2 = el4.z + er4.z; e2 = e2 > 0.f ? e2 : NEG_SLOPE * e2;
        float e3 = el4.w + er4.w; e3 = e3 > 0.f ? e3 : NEG_SLOPE * e3;
        mx.x = fmaxf(mx.x, e0); mx.y = fmaxf(mx.y, e1);
        mx.z = fmaxf(mx.z, e2); mx.w = fmaxf(mx.w, e3);
    }
#pragma unroll
    for (int o = 16; o >= 1; o >>= 1) {
        mx.x = fmaxf(mx.x, __shfl_xor_sync(0xffffffffu, mx.x, o));
        mx.y = fmaxf(mx.y, __shfl_xor_sync(0xffffffffu, mx.y, o));
        mx.z = fmaxf(mx.z, __shfl_xor_sync(0xffffffffu, mx.z, o));
        mx.w = fmaxf(mx.w, __shfl_xor_sync(0xffffffffu, mx.w, o));
    }
    float mh  = (h == 0) ? mx.x : (h == 1) ? mx.y : (h == 2) ? mx.z : mx.w;
    float erh = (h == 0) ? er4.x : (h == 1) ? er4.y : (h == 2) ? er4.z : er4.w;

    // ---- pass 2: exp-weighted accumulate (whole warp per edge) ----
    float4 acc = make_float4(0.f, 0.f, 0.f, 0.f);
    float denom = 0.f;
    for (int i = begin; i < end; i++) {
        int e = g_eidx[i];          // broadcast
        int s = src[e];             // broadcast
        float ev = g_el[s * HEADS + h] + erh;
        ev = ev > 0.f ? ev : NEG_SLOPE * ev;
        float w = __expf(ev - mh);
        denom += w;
        float4 f = *(const float4*)&g_feat[(size_t)s * FEAT_DIM + lane * 4];
        acc.x += w * f.x; acc.y += w * f.y;
        acc.z += w * f.z; acc.w += w * f.w;
    }
    float inv = 0.25f / fmaxf(denom, 1e-9f);
    acc.x *= inv; acc.y *= inv; acc.z *= inv; acc.w *= inv;

    // ---- sum across the 4 heads (lane bits 3,4) ----
#pragma unroll
    for (int o = 8; o <= 16; o <<= 1) {
        acc.x += __shfl_xor_sync(0xffffffffu, acc.x, o);
        acc.y += __shfl_xor_sync(0xffffffffu, acc.y, o);
        acc.z += __shfl_xor_sync(0xffffffffu, acc.z, o);
        acc.w += __shfl_xor_sync(0xffffffffu, acc.w, o);
    }
    if (lane < 8) {
        *(float4*)&out[(size_t)n * OUT_DIM + q * 4] = acc;
    }
}

// ---------------- launch ---------------------------------------------------
extern "C" void kernel_launch(void* const* d_in, const int* in_sizes, int n_in,
                              void* d_out, int out_size) {
    const float* x      = (const float*)d_in[0];
    const float* W      = (const float*)d_in[1];
    const float* attn_l = (const float*)d_in[2];
    const float* attn_r = (const float*)d_in[3];
    const int*   src    = (const int*)d_in[4];
    const int*   dst    = (const int*)d_in[5];
    float* out = (float*)d_out;

    gemm_kernel<<<(N_NODES + BM - 1) / BM, 256>>>(x, W);
    elr_kernel<<<(N_NODES * 32 + 255) / 256, 256>>>(attn_l, attn_r);
    zero_deg_kernel<<<(N_NODES + 255) / 256, 256>>>();
    hist_kernel<<<(N_EDGES + 255) / 256, 256>>>(dst);
    scan1_kernel<<<NB, SCAN_B>>>();
    scan2_kernel<<<1, 128>>>();
    scan3_kernel<<<(N_NODES + 255) / 256, 256>>>();
    scatter_kernel<<<(N_EDGES + 255) / 256, 256>>>(dst);
    aggregate_kernel<<<(N_NODES * 32 + 255) / 256, 256>>>(src, out);
}

// round 3
// speedup vs baseline: 1.6429x; 1.6429x over previous
#include <cuda_runtime.h>
#include <cuda_bf16.h>
#include <math_constants.h>
#include <cstdint>

#define N_NODES 100000
#define N_EDGES 1600000
#define IN_DIM 256
#define HEADS 4
#define OUT_DIM 32
#define FEAT_DIM 128
#define NEG_SLOPE 0.2f

#define SCAN_B 1024
#define NB ((N_NODES + SCAN_B - 1) / SCAN_B)

// ---------------- scratch ---------------------------------------------------
__device__ float g_feat[(size_t)N_NODES * FEAT_DIM];
__device__ float g_el[N_NODES * HEADS];
__device__ float g_er[N_NODES * HEADS];
__device__ int   g_deg[N_NODES];
__device__ int   g_off[N_NODES + 1];
__device__ int   g_cur[N_NODES];
__device__ int   g_esrc[N_EDGES];
__device__ int   g_bsums[128];
__device__ __nv_bfloat16 g_WhT[FEAT_DIM * IN_DIM];   // [n=128][k=256] row-major (B^T)
__device__ __nv_bfloat16 g_WlT[FEAT_DIM * IN_DIM];

// ---------------- helpers ---------------------------------------------------
__device__ __forceinline__ uint32_t smem_u32(const void* p) {
    uint32_t a;
    asm("{ .reg .u64 t; cvta.to.shared.u64 t, %1; cvt.u32.u64 %0, t; }" : "=r"(a) : "l"(p));
    return a;
}
__device__ __forceinline__ void ldm_x4(uint32_t* r, uint32_t addr) {
    asm volatile("ldmatrix.sync.aligned.m8n8.x4.shared.b16 {%0,%1,%2,%3}, [%4];"
        : "=r"(r[0]), "=r"(r[1]), "=r"(r[2]), "=r"(r[3]) : "r"(addr));
}
__device__ __forceinline__ void ldm_x2(uint32_t* r, uint32_t addr) {
    asm volatile("ldmatrix.sync.aligned.m8n8.x2.shared.b16 {%0,%1}, [%2];"
        : "=r"(r[0]), "=r"(r[1]) : "r"(addr));
}
__device__ __forceinline__ void mma_bf16(float* c, const uint32_t* a, const uint32_t* b) {
    asm volatile("mma.sync.aligned.m16n8k16.row.col.f32.bf16.bf16.f32 "
        "{%0,%1,%2,%3}, {%4,%5,%6,%7}, {%8,%9}, {%0,%1,%2,%3};"
        : "+f"(c[0]), "+f"(c[1]), "+f"(c[2]), "+f"(c[3])
        : "r"(a[0]), "r"(a[1]), "r"(a[2]), "r"(a[3]), "r"(b[0]), "r"(b[1]));
}

// ---------------- W transpose + bf16 split ----------------------------------
__global__ void wsplit_kernel(const float* __restrict__ W) {
    int i = blockIdx.x * blockDim.x + threadIdx.x;
    if (i < IN_DIM * FEAT_DIM) {
        int k = i / FEAT_DIM, n = i % FEAT_DIM;
        float w = W[i];
        __nv_bfloat16 h = __float2bfloat16(w);
        float r = w - __bfloat162float(h);
        g_WhT[n * IN_DIM + k] = h;
        g_WlT[n * IN_DIM + k] = __float2bfloat16(r);
    }
}

// ---------------- split-bf16 HMMA GEMM + fused el/er epilogue ----------------
// CTA tile: 128 rows x 128 cols, K chunks of 32. 8 warps (4x2), warp tile 32x64.
#define APAD 40   // 32 + 8 bf16 pad -> 80B row stride, conflict-free ldmatrix

__global__ __launch_bounds__(256) void gemm_mma_kernel(const float* __restrict__ A,
                                                       const float* __restrict__ attn_l,
                                                       const float* __restrict__ attn_r) {
    __shared__ __align__(16) __nv_bfloat16 Ash[128][APAD];
    __shared__ __align__(16) __nv_bfloat16 Asl[128][APAD];
    __shared__ __align__(16) __nv_bfloat16 Bsh[128][APAD];
    __shared__ __align__(16) __nv_bfloat16 Bsl[128][APAD];
    __shared__ float al_s[128], ar_s[128];

    const int tid = threadIdx.x;
    const int wid = tid >> 5;
    const int lane = tid & 31;
    const int warp_m = wid >> 1;     // 0..3
    const int warp_n = wid & 1;      // 0..1
    const int blockRow = blockIdx.x * 128;

    if (tid < 128) { al_s[tid] = attn_l[tid]; ar_s[tid] = attn_r[tid]; }

    // per-thread staging coords
    const int ld_row = tid >> 1;            // 0..127
    const int ld_koff = (tid & 1) * 16;     // 0 or 16

    int grow = blockRow + ld_row;
    if (grow >= N_NODES) grow = N_NODES - 1;
    const float4* aptr = (const float4*)(A + (size_t)grow * IN_DIM + ld_koff);
    const uint4* bhp = (const uint4*)(g_WhT + ld_row * IN_DIM + ld_koff);
    const uint4* blp = (const uint4*)(g_WlT + ld_row * IN_DIM + ld_koff);

    float c[2][8][4];
#pragma unroll
    for (int mt = 0; mt < 2; mt++)
#pragma unroll
        for (int nt = 0; nt < 8; nt++)
#pragma unroll
            for (int j = 0; j < 4; j++) c[mt][nt][j] = 0.f;

    const uint32_t ash_b = smem_u32(&Ash[0][0]);
    const uint32_t asl_b = smem_u32(&Asl[0][0]);
    const uint32_t bsh_b = smem_u32(&Bsh[0][0]);
    const uint32_t bsl_b = smem_u32(&Bsl[0][0]);

    for (int kc = 0; kc < 8; kc++) {
        // -------- gmem -> regs --------
        float4 f[4];
#pragma unroll
        for (int j = 0; j < 4; j++) f[j] = aptr[kc * 8 + j];
        uint4 bh0 = bhp[kc * 4 + 0], bh1 = bhp[kc * 4 + 1];
        uint4 bl0 = blp[kc * 4 + 0], bl1 = blp[kc * 4 + 1];

        // split A fp32 -> bf16 hi/lo
        uint32_t hw[8], lw[8];
        const float* ff = (const float*)f;
#pragma unroll
        for (int j = 0; j < 8; j++) {
            float x0 = ff[2 * j], x1 = ff[2 * j + 1];
            __nv_bfloat16 h0 = __float2bfloat16(x0);
            __nv_bfloat16 h1 = __float2bfloat16(x1);
            __nv_bfloat16 l0 = __float2bfloat16(x0 - __bfloat162float(h0));
            __nv_bfloat16 l1 = __float2bfloat16(x1 - __bfloat162float(h1));
            hw[j] = (uint32_t)__bfloat16_as_ushort(h0) | ((uint32_t)__bfloat16_as_ushort(h1) << 16);
            lw[j] = (uint32_t)__bfloat16_as_ushort(l0) | ((uint32_t)__bfloat16_as_ushort(l1) << 16);
        }

        __syncthreads();   // prev chunk compute done

        *(uint4*)&Ash[ld_row][ld_koff]     = make_uint4(hw[0], hw[1], hw[2], hw[3]);
        *(uint4*)&Ash[ld_row][ld_koff + 8] = make_uint4(hw[4], hw[5], hw[6], hw[7]);
        *(uint4*)&Asl[ld_row][ld_koff]     = make_uint4(lw[0], lw[1], lw[2], lw[3]);
        *(uint4*)&Asl[ld_row][ld_koff + 8] = make_uint4(lw[4], lw[5], lw[6], lw[7]);
        *(uint4*)&Bsh[ld_row][ld_koff]     = bh0;
        *(uint4*)&Bsh[ld_row][ld_koff + 8] = bh1;
        *(uint4*)&Bsl[ld_row][ld_koff]     = bl0;
        *(uint4*)&Bsl[ld_row][ld_koff + 8] = bl1;

        __syncthreads();

        // -------- compute: 2 k16-steps --------
#pragma unroll
        for (int ks = 0; ks < 2; ks++) {
            const int k0 = ks * 16;
            uint32_t ah[2][4], al[2][4];
#pragma unroll
            for (int mt = 0; mt < 2; mt++) {
                int r = warp_m * 32 + mt * 16 + (lane & 7) + ((lane >> 3) & 1) * 8;
                int cc = k0 + ((lane >> 4) & 1) * 8;
                uint32_t off = (uint32_t)(r * APAD + cc) * 2;
                ldm_x4(ah[mt], ash_b + off);
                ldm_x4(al[mt], asl_b + off);
            }
            uint32_t bh[8][2], bl[8][2];
#pragma unroll
            for (int nt = 0; nt < 8; nt++) {
                int n = warp_n * 64 + nt * 8 + (lane & 7);
                int cc = k0 + ((lane >> 3) & 1) * 8;
                uint32_t off = (uint32_t)(n * APAD + cc) * 2;
                ldm_x2(bh[nt], bsh_b + off);
                ldm_x2(bl[nt], bsl_b + off);
            }
#pragma unroll
            for (int mt = 0; mt < 2; mt++)
#pragma unroll
                for (int nt = 0; nt < 8; nt++) {
                    mma_bf16(c[mt][nt], ah[mt], bh[nt]);
                    mma_bf16(c[mt][nt], al[mt], bh[nt]);
                    mma_bf16(c[mt][nt], ah[mt], bl[nt]);
                }
        }
    }

    // -------- epilogue: store feat + fused el/er --------
#pragma unroll
    for (int mt = 0; mt < 2; mt++) {
        float el_[2][2] = {{0.f, 0.f}, {0.f, 0.f}};
        float er_[2][2] = {{0.f, 0.f}, {0.f, 0.f}};
        int row0 = blockRow + warp_m * 32 + mt * 16 + (lane >> 2);
#pragma unroll
        for (int nt = 0; nt < 8; nt++) {
            int hl = nt >> 2;
            int col = warp_n * 64 + nt * 8 + (lane & 3) * 2;
            float c0 = c[mt][nt][0], c1 = c[mt][nt][1];
            float c2 = c[mt][nt][2], c3 = c[mt][nt][3];
            float a0 = al_s[col], a1 = al_s[col + 1];
            float r0 = ar_s[col], r1 = ar_s[col + 1];
            el_[0][hl] += c0 * a0 + c1 * a1;
            er_[0][hl] += c0 * r0 + c1 * r1;
            el_[1][hl] += c2 * a0 + c3 * a1;
            er_[1][hl] += c2 * r0 + c3 * r1;
            if (row0 < N_NODES)
                *(float2*)&g_feat[(size_t)row0 * FEAT_DIM + col] = make_float2(c0, c1);
            if (row0 + 8 < N_NODES)
                *(float2*)&g_feat[(size_t)(row0 + 8) * FEAT_DIM + col] = make_float2(c2, c3);
        }
#pragma unroll
        for (int rh = 0; rh < 2; rh++)
#pragma unroll
            for (int hl = 0; hl < 2; hl++) {
                float v = el_[rh][hl];
                float w = er_[rh][hl];
                v += __shfl_xor_sync(0xffffffffu, v, 1);
                v += __shfl_xor_sync(0xffffffffu, v, 2);
                w += __shfl_xor_sync(0xffffffffu, w, 1);
                w += __shfl_xor_sync(0xffffffffu, w, 2);
                int row = row0 + rh * 8;
                if ((lane & 3) == 0 && row < N_NODES) {
                    g_el[row * HEADS + warp_n * 2 + hl] = v;
                    g_er[row * HEADS + warp_n * 2 + hl] = w;
                }
            }
    }
}

// ---------------- CSR build ------------------------------------------------
__global__ void zero_deg_kernel() {
    int i = blockIdx.x * blockDim.x + threadIdx.x;
    if (i < N_NODES / 4) ((int4*)g_deg)[i] = make_int4(0, 0, 0, 0);
}

__global__ void hist_kernel(const int* __restrict__ dst) {
    int i = blockIdx.x * blockDim.x + threadIdx.x;
    if (i < N_EDGES / 4) {
        int4 d = ((const int4*)dst)[i];
        atomicAdd(&g_deg[d.x], 1);
        atomicAdd(&g_deg[d.y], 1);
        atomicAdd(&g_deg[d.z], 1);
        atomicAdd(&g_deg[d.w], 1);
    }
}

__global__ __launch_bounds__(SCAN_B) void scan1_kernel() {
    __shared__ int wsum[32];
    int i = blockIdx.x * SCAN_B + threadIdx.x;
    int lane = threadIdx.x & 31;
    int wid = threadIdx.x >> 5;
    int v = (i < N_NODES) ? g_deg[i] : 0;
    int x = v;
#pragma unroll
    for (int o = 1; o < 32; o <<= 1) {
        int y = __shfl_up_sync(0xffffffffu, x, o);
        if (lane >= o) x += y;
    }
    if (lane == 31) wsum[wid] = x;
    __syncthreads();
    if (threadIdx.x < 32) {
        int w = wsum[threadIdx.x];
#pragma unroll
        for (int o = 1; o < 32; o <<= 1) {
            int y = __shfl_up_sync(0xffffffffu, w, o);
            if ((int)threadIdx.x >= o) w += y;
        }
        wsum[threadIdx.x] = w;
    }
    __syncthreads();
    int base = wid ? wsum[wid - 1] : 0;
    int incl = x + base;
    if (i < N_NODES) g_off[i] = incl;
    if (threadIdx.x == SCAN_B - 1) g_bsums[blockIdx.x] = incl;
}

__global__ void scan2_kernel() {
    __shared__ int ws[4];
    int t = threadIdx.x;
    int lane = t & 31;
    int wid = t >> 5;
    int v = (t < NB) ? g_bsums[t] : 0;
    int x = v;
#pragma unroll
    for (int o = 1; o < 32; o <<= 1) {
        int y = __shfl_up_sync(0xffffffffu, x, o);
        if (lane >= o) x += y;
    }
    if (lane == 31) ws[wid] = x;
    __syncthreads();
    int base = 0;
    for (int w = 0; w < wid; w++) base += ws[w];
    g_bsums[t] = x + base;
}

__global__ void scan3_kernel() {
    int i = blockIdx.x * blockDim.x + threadIdx.x;
    if (i < N_NODES) {
        int b = i >> 10;
        int add = b ? g_bsums[b - 1] : 0;
        int incl = g_off[i] + add;
        int excl = incl - g_deg[i];
        g_off[i] = excl;
        g_cur[i] = excl;
        if (i == 0) g_off[N_NODES] = g_bsums[NB - 1];
    }
}

__global__ void scatter_kernel(const int* __restrict__ dst, const int* __restrict__ src) {
    int i = blockIdx.x * blockDim.x + threadIdx.x;
    if (i < N_EDGES / 4) {
        int4 d = ((const int4*)dst)[i];
        int4 s = ((const int4*)src)[i];
        g_esrc[atomicAdd(&g_cur[d.x], 1)] = s.x;
        g_esrc[atomicAdd(&g_cur[d.y], 1)] = s.y;
        g_esrc[atomicAdd(&g_cur[d.z], 1)] = s.z;
        g_esrc[atomicAdd(&g_cur[d.w], 1)] = s.w;
    }
}

// ---------------- fused single-pass softmax + aggregation -------------------
__global__ __launch_bounds__(256) void aggregate_kernel(float* __restrict__ out) {
    int n = (blockIdx.x * blockDim.x + threadIdx.x) >> 5;
    int lane = threadIdx.x & 31;
    if (n >= N_NODES) return;
    int h = lane >> 3;
    int q = lane & 7;

    int begin = g_off[n];
    int end = g_off[n + 1];
    float erh = g_er[n * HEADS + h];

    float4 acc = make_float4(0.f, 0.f, 0.f, 0.f);
    float denom = 0.f;
    int i = begin;
    for (; i + 2 <= end; i += 2) {
        int s0 = g_esrc[i];
        int s1 = g_esrc[i + 1];
        float e0 = g_el[s0 * HEADS + h] + erh;
        float e1 = g_el[s1 * HEADS + h] + erh;
        e0 = e0 > 0.f ? e0 : NEG_SLOPE * e0;
        e1 = e1 > 0.f ? e1 : NEG_SLOPE * e1;
        float w0 = __expf(e0);
        float w1 = __expf(e1);
        float4 f0 = *(const float4*)&g_feat[(size_t)s0 * FEAT_DIM + lane * 4];
        float4 f1 = *(const float4*)&g_feat[(size_t)s1 * FEAT_DIM + lane * 4];
        denom += w0 + w1;
        acc.x += w0 * f0.x + w1 * f1.x;
        acc.y += w0 * f0.y + w1 * f1.y;
        acc.z += w0 * f0.z + w1 * f1.z;
        acc.w += w0 * f0.w + w1 * f1.w;
    }
    if (i < end) {
        int s0 = g_esrc[i];
        float e0 = g_el[s0 * HEADS + h] + erh;
        e0 = e0 > 0.f ? e0 : NEG_SLOPE * e0;
        float w0 = __expf(e0);
        float4 f0 = *(const float4*)&g_feat[(size_t)s0 * FEAT_DIM + lane * 4];
        denom += w0;
        acc.x += w0 * f0.x;
        acc.y += w0 * f0.y;
        acc.z += w0 * f0.z;
        acc.w += w0 * f0.w;
    }
    float inv = 0.25f / fmaxf(denom, 1e-9f);
    acc.x *= inv; acc.y *= inv; acc.z *= inv; acc.w *= inv;

#pragma unroll
    for (int o = 8; o <= 16; o <<= 1) {
        acc.x += __shfl_xor_sync(0xffffffffu, acc.x, o);
        acc.y += __shfl_xor_sync(0xffffffffu, acc.y, o);
        acc.z += __shfl_xor_sync(0xffffffffu, acc.z, o);
        acc.w += __shfl_xor_sync(0xffffffffu, acc.w, o);
    }
    if (lane < 8) {
        *(float4*)&out[(size_t)n * OUT_DIM + q * 4] = acc;
    }
}

// ---------------- launch ---------------------------------------------------
extern "C" void kernel_launch(void* const* d_in, const int* in_sizes, int n_in,
                              void* d_out, int out_size) {
    const float* x = (const float*)d_in[0];
    const float* W = (const float*)d_in[1];
    const float* attn_l = (const float*)d_in[2];
    const float* attn_r = (const float*)d_in[3];
    const int* src = (const int*)d_in[4];
    const int* dst = (const int*)d_in[5];
    float* out = (float*)d_out;

    wsplit_kernel<<<(IN_DIM * FEAT_DIM + 255) / 256, 256>>>(W);
    gemm_mma_kernel<<<(N_NODES + 127) / 128, 256>>>(x, attn_l, attn_r);
    zero_deg_kernel<<<(N_NODES / 4 + 255) / 256, 256>>>();
    hist_kernel<<<(N_EDGES / 4 + 255) / 256, 256>>>(dst);
    scan1_kernel<<<NB, SCAN_B>>>();
    scan2_kernel<<<1, 128>>>();
    scan3_kernel<<<(N_NODES + 255) / 256, 256>>>();
    scatter_kernel<<<(N_EDGES / 4 + 255) / 256, 256>>>(dst, src);
    aggregate_kernel<<<(N_NODES * 32 + 255) / 256, 256>>>(out);
}

// round 4
// speedup vs baseline: 1.7332x; 1.0550x over previous
#include <cuda_runtime.h>
#include <cuda_bf16.h>
#include <math_constants.h>
#include <cstdint>

#define N_NODES 100000
#define N_EDGES 1600000
#define IN_DIM 256
#define HEADS 4
#define OUT_DIM 32
#define FEAT_DIM 128
#define NEG_SLOPE 0.2f

#define SCAN_B 1024
#define NB ((N_NODES + SCAN_B - 1) / SCAN_B)

// ---------------- scratch ---------------------------------------------------
__device__ float g_feat[(size_t)N_NODES * FEAT_DIM];
__device__ float g_el[N_NODES * HEADS];
__device__ float g_er[N_NODES * HEADS];
__device__ int   g_deg[N_NODES];
__device__ int   g_off[N_NODES + 1];
__device__ int   g_cur[N_NODES];
__device__ int   g_esrc[N_EDGES];
__device__ int   g_bsums[128];
__device__ __nv_bfloat16 g_WhT[FEAT_DIM * IN_DIM];   // [n=128][k=256] (B^T)
__device__ __nv_bfloat16 g_WlT[FEAT_DIM * IN_DIM];

// ---------------- helpers ---------------------------------------------------
__device__ __forceinline__ uint32_t smem_u32(const void* p) {
    uint32_t a;
    asm("{ .reg .u64 t; cvta.to.shared.u64 t, %1; cvt.u32.u64 %0, t; }" : "=r"(a) : "l"(p));
    return a;
}
__device__ __forceinline__ void ldm_x4(uint32_t* r, uint32_t addr) {
    asm volatile("ldmatrix.sync.aligned.m8n8.x4.shared.b16 {%0,%1,%2,%3}, [%4];"
        : "=r"(r[0]), "=r"(r[1]), "=r"(r[2]), "=r"(r[3]) : "r"(addr));
}
__device__ __forceinline__ void ldm_x2(uint32_t* r, uint32_t addr) {
    asm volatile("ldmatrix.sync.aligned.m8n8.x2.shared.b16 {%0,%1}, [%2];"
        : "=r"(r[0]), "=r"(r[1]) : "r"(addr));
}
__device__ __forceinline__ void mma_bf16(float* c, const uint32_t* a, const uint32_t* b) {
    asm volatile("mma.sync.aligned.m16n8k16.row.col.f32.bf16.bf16.f32 "
        "{%0,%1,%2,%3}, {%4,%5,%6,%7}, {%8,%9}, {%0,%1,%2,%3};"
        : "+f"(c[0]), "+f"(c[1]), "+f"(c[2]), "+f"(c[3])
        : "r"(a[0]), "r"(a[1]), "r"(a[2]), "r"(a[3]), "r"(b[0]), "r"(b[1]));
}

// ---------------- W transpose + bf16 split ----------------------------------
__global__ void wsplit_kernel(const float* __restrict__ W) {
    int i = blockIdx.x * blockDim.x + threadIdx.x;
    if (i < IN_DIM * FEAT_DIM) {
        int k = i / FEAT_DIM, n = i % FEAT_DIM;
        float w = W[i];
        __nv_bfloat16 h = __float2bfloat16(w);
        float r = w - __bfloat162float(h);
        g_WhT[n * IN_DIM + k] = h;
        g_WlT[n * IN_DIM + k] = __float2bfloat16(r);
    }
}

// ---------------- split-bf16 HMMA GEMM: B-resident + double-buffered A ------
#define B_STRIDE 264   // 256 + 8 pad -> 528B row = 33*16B (odd), conflict-free
#define A_STRIDE 40    // 32 + 8 pad  -> 80B row  = 5*16B  (odd)
#define SM_BH 0
#define SM_BL (128 * B_STRIDE * 2)              // 67584
#define SM_AH (SM_BL + 128 * B_STRIDE * 2)      // 135168
#define SM_AL (SM_AH + 2 * 128 * A_STRIDE * 2)  // 155648
#define SM_ALS (SM_AL + 2 * 128 * A_STRIDE * 2) // 176128
#define SM_ARS (SM_ALS + 512)
#define GEMM_SMEM (SM_ARS + 512)                // 177152

__device__ __forceinline__ void split16(const float4* f, uint32_t* hw, uint32_t* lw) {
    const float* ff = (const float*)f;
#pragma unroll
    for (int j = 0; j < 8; j++) {
        float x0 = ff[2 * j], x1 = ff[2 * j + 1];
        __nv_bfloat16 h0 = __float2bfloat16(x0);
        __nv_bfloat16 h1 = __float2bfloat16(x1);
        __nv_bfloat16 l0 = __float2bfloat16(x0 - __bfloat162float(h0));
        __nv_bfloat16 l1 = __float2bfloat16(x1 - __bfloat162float(h1));
        hw[j] = (uint32_t)__bfloat16_as_ushort(h0) | ((uint32_t)__bfloat16_as_ushort(h1) << 16);
        lw[j] = (uint32_t)__bfloat16_as_ushort(l0) | ((uint32_t)__bfloat16_as_ushort(l1) << 16);
    }
}

__global__ __launch_bounds__(256, 1) void gemm_mma_kernel(const float* __restrict__ A,
                                                          const float* __restrict__ attn_l,
                                                          const float* __restrict__ attn_r) {
    extern __shared__ char smem[];
    __nv_bfloat16* Bh = (__nv_bfloat16*)(smem + SM_BH);
    __nv_bfloat16* Bl = (__nv_bfloat16*)(smem + SM_BL);
    float* al_s = (float*)(smem + SM_ALS);
    float* ar_s = (float*)(smem + SM_ARS);

    const int tid = threadIdx.x;
    const int wid = tid >> 5;
    const int lane = tid & 31;
    const int warp_m = wid >> 1;
    const int warp_n = wid & 1;
    const int blockRow = blockIdx.x * 128;

    // ---- B resident load (once) ----
#pragma unroll
    for (int it = 0; it < 16; it++) {
        int idx = tid + it * 256;          // 0..4095
        int row = idx >> 5, seg = idx & 31;
        *(uint4*)&Bh[row * B_STRIDE + seg * 8] = *(const uint4*)&g_WhT[row * 256 + seg * 8];
        *(uint4*)&Bl[row * B_STRIDE + seg * 8] = *(const uint4*)&g_WlT[row * 256 + seg * 8];
    }
    if (tid < 128) { al_s[tid] = attn_l[tid]; ar_s[tid] = attn_r[tid]; }

    // ---- A staging coords ----
    const int ld_row = tid >> 1;
    const int ld_koff = (tid & 1) * 16;
    int grow = blockRow + ld_row;
    if (grow >= N_NODES) grow = N_NODES - 1;
    const float4* aptr = (const float4*)(A + (size_t)grow * IN_DIM + ld_koff);

    const uint32_t ah_b = smem_u32(smem + SM_AH);
    const uint32_t al_b = smem_u32(smem + SM_AL);
    const uint32_t bh_b = smem_u32(smem + SM_BH);
    const uint32_t bl_b = smem_u32(smem + SM_BL);
    const uint32_t abuf_bytes = 128 * A_STRIDE * 2;

    float c[2][8][4];
#pragma unroll
    for (int mt = 0; mt < 2; mt++)
#pragma unroll
        for (int nt = 0; nt < 8; nt++)
#pragma unroll
            for (int j = 0; j < 4; j++) c[mt][nt][j] = 0.f;

    // ---- prologue: chunk 0 -> buf 0 ----
    {
        float4 f[4];
#pragma unroll
        for (int j = 0; j < 4; j++) f[j] = aptr[j];
        uint32_t hw[8], lw[8];
        split16(f, hw, lw);
        __nv_bfloat16* Ah0 = (__nv_bfloat16*)(smem + SM_AH);
        __nv_bfloat16* Al0 = (__nv_bfloat16*)(smem + SM_AL);
        *(uint4*)&Ah0[ld_row * A_STRIDE + ld_koff]     = make_uint4(hw[0], hw[1], hw[2], hw[3]);
        *(uint4*)&Ah0[ld_row * A_STRIDE + ld_koff + 8] = make_uint4(hw[4], hw[5], hw[6], hw[7]);
        *(uint4*)&Al0[ld_row * A_STRIDE + ld_koff]     = make_uint4(lw[0], lw[1], lw[2], lw[3]);
        *(uint4*)&Al0[ld_row * A_STRIDE + ld_koff + 8] = make_uint4(lw[4], lw[5], lw[6], lw[7]);
    }
    __syncthreads();

    for (int kc = 0; kc < 8; kc++) {
        // issue next chunk's gmem loads before compute
        float4 fn[4];
        if (kc < 7) {
#pragma unroll
            for (int j = 0; j < 4; j++) fn[j] = aptr[(kc + 1) * 8 + j];
        }
        const uint32_t abase_h = ah_b + (kc & 1) * abuf_bytes;
        const uint32_t abase_l = al_b + (kc & 1) * abuf_bytes;

#pragma unroll
        for (int ks = 0; ks < 2; ks++) {
            const int k0 = ks * 16;
            uint32_t ah[2][4], al[2][4];
#pragma unroll
            for (int mt = 0; mt < 2; mt++) {
                int r = warp_m * 32 + mt * 16 + (lane & 15);
                int cc = k0 + ((lane >> 4) & 1) * 8;
                uint32_t off = (uint32_t)(r * A_STRIDE + cc) * 2;
                ldm_x4(ah[mt], abase_h + off);
                ldm_x4(al[mt], abase_l + off);
            }
            uint32_t bhf[8][2], blf[8][2];
#pragma unroll
            for (int nt = 0; nt < 8; nt++) {
                int n = warp_n * 64 + nt * 8 + (lane & 7);
                int cc = kc * 32 + k0 + ((lane >> 3) & 1) * 8;
                uint32_t off = (uint32_t)(n * B_STRIDE + cc) * 2;
                ldm_x2(bhf[nt], bh_b + off);
                ldm_x2(blf[nt], bl_b + off);
            }
#pragma unroll
            for (int mt = 0; mt < 2; mt++)
#pragma unroll
                for (int nt = 0; nt < 8; nt++) {
                    mma_bf16(c[mt][nt], ah[mt], bhf[nt]);
                    mma_bf16(c[mt][nt], al[mt], bhf[nt]);
                    mma_bf16(c[mt][nt], ah[mt], blf[nt]);
                }
        }

        if (kc < 7) {
            uint32_t hw[8], lw[8];
            split16(fn, hw, lw);
            __nv_bfloat16* Ahn = (__nv_bfloat16*)(smem + SM_AH + ((kc + 1) & 1) * abuf_bytes);
            __nv_bfloat16* Aln = (__nv_bfloat16*)(smem + SM_AL + ((kc + 1) & 1) * abuf_bytes);
            *(uint4*)&Ahn[ld_row * A_STRIDE + ld_koff]     = make_uint4(hw[0], hw[1], hw[2], hw[3]);
            *(uint4*)&Ahn[ld_row * A_STRIDE + ld_koff + 8] = make_uint4(hw[4], hw[5], hw[6], hw[7]);
            *(uint4*)&Aln[ld_row * A_STRIDE + ld_koff]     = make_uint4(lw[0], lw[1], lw[2], lw[3]);
            *(uint4*)&Aln[ld_row * A_STRIDE + ld_koff + 8] = make_uint4(lw[4], lw[5], lw[6], lw[7]);
        }
        __syncthreads();
    }

    // ---- epilogue: store feat + fused el/er ----
#pragma unroll
    for (int mt = 0; mt < 2; mt++) {
        float el_[2][2] = {{0.f, 0.f}, {0.f, 0.f}};
        float er_[2][2] = {{0.f, 0.f}, {0.f, 0.f}};
        int row0 = blockRow + warp_m * 32 + mt * 16 + (lane >> 2);
#pragma unroll
        for (int nt = 0; nt < 8; nt++) {
            int hl = nt >> 2;
            int col = warp_n * 64 + nt * 8 + (lane & 3) * 2;
            float c0 = c[mt][nt][0], c1 = c[mt][nt][1];
            float c2 = c[mt][nt][2], c3 = c[mt][nt][3];
            float a0 = al_s[col], a1 = al_s[col + 1];
            float r0 = ar_s[col], r1 = ar_s[col + 1];
            el_[0][hl] += c0 * a0 + c1 * a1;
            er_[0][hl] += c0 * r0 + c1 * r1;
            el_[1][hl] += c2 * a0 + c3 * a1;
            er_[1][hl] += c2 * r0 + c3 * r1;
            if (row0 < N_NODES)
                *(float2*)&g_feat[(size_t)row0 * FEAT_DIM + col] = make_float2(c0, c1);
            if (row0 + 8 < N_NODES)
                *(float2*)&g_feat[(size_t)(row0 + 8) * FEAT_DIM + col] = make_float2(c2, c3);
        }
#pragma unroll
        for (int rh = 0; rh < 2; rh++)
#pragma unroll
            for (int hl = 0; hl < 2; hl++) {
                float v = el_[rh][hl];
                float w = er_[rh][hl];
                v += __shfl_xor_sync(0xffffffffu, v, 1);
                v += __shfl_xor_sync(0xffffffffu, v, 2);
                w += __shfl_xor_sync(0xffffffffu, w, 1);
                w += __shfl_xor_sync(0xffffffffu, w, 2);
                int row = row0 + rh * 8;
                if ((lane & 3) == 0 && row < N_NODES) {
                    g_el[row * HEADS + warp_n * 2 + hl] = v;
                    g_er[row * HEADS + warp_n * 2 + hl] = w;
                }
            }
    }
}

// ---------------- CSR build ------------------------------------------------
__global__ void zero_deg_kernel() {
    int i = blockIdx.x * blockDim.x + threadIdx.x;
    if (i < N_NODES / 4) ((int4*)g_deg)[i] = make_int4(0, 0, 0, 0);
}

__global__ void hist_kernel(const int* __restrict__ dst) {
    int i = blockIdx.x * blockDim.x + threadIdx.x;
    if (i < N_EDGES / 4) {
        int4 d = ((const int4*)dst)[i];
        atomicAdd(&g_deg[d.x], 1);
        atomicAdd(&g_deg[d.y], 1);
        atomicAdd(&g_deg[d.z], 1);
        atomicAdd(&g_deg[d.w], 1);
    }
}

__global__ __launch_bounds__(SCAN_B) void scan1_kernel() {
    __shared__ int wsum[32];
    int i = blockIdx.x * SCAN_B + threadIdx.x;
    int lane = threadIdx.x & 31;
    int wid = threadIdx.x >> 5;
    int v = (i < N_NODES) ? g_deg[i] : 0;
    int x = v;
#pragma unroll
    for (int o = 1; o < 32; o <<= 1) {
        int y = __shfl_up_sync(0xffffffffu, x, o);
        if (lane >= o) x += y;
    }
    if (lane == 31) wsum[wid] = x;
    __syncthreads();
    if (threadIdx.x < 32) {
        int w = wsum[threadIdx.x];
#pragma unroll
        for (int o = 1; o < 32; o <<= 1) {
            int y = __shfl_up_sync(0xffffffffu, w, o);
            if ((int)threadIdx.x >= o) w += y;
        }
        wsum[threadIdx.x] = w;
    }
    __syncthreads();
    int base = wid ? wsum[wid - 1] : 0;
    int incl = x + base;
    if (i < N_NODES) g_off[i] = incl;
    if (threadIdx.x == SCAN_B - 1) g_bsums[blockIdx.x] = incl;
}

__global__ void scan2_kernel() {
    __shared__ int ws[4];
    int t = threadIdx.x;
    int lane = t & 31;
    int wid = t >> 5;
    int v = (t < NB) ? g_bsums[t] : 0;
    int x = v;
#pragma unroll
    for (int o = 1; o < 32; o <<= 1) {
        int y = __shfl_up_sync(0xffffffffu, x, o);
        if (lane >= o) x += y;
    }
    if (lane == 31) ws[wid] = x;
    __syncthreads();
    int base = 0;
    for (int w = 0; w < wid; w++) base += ws[w];
    g_bsums[t] = x + base;
}

__global__ void scan3_kernel() {
    int i = blockIdx.x * blockDim.x + threadIdx.x;
    if (i < N_NODES) {
        int b = i >> 10;
        int add = b ? g_bsums[b - 1] : 0;
        int incl = g_off[i] + add;
        int excl = incl - g_deg[i];
        g_off[i] = excl;
        g_cur[i] = excl;
        if (i == 0) g_off[N_NODES] = g_bsums[NB - 1];
    }
}

__global__ void scatter_kernel(const int* __restrict__ dst, const int* __restrict__ src) {
    int i = blockIdx.x * blockDim.x + threadIdx.x;
    if (i < N_EDGES / 4) {
        int4 d = ((const int4*)dst)[i];
        int4 s = ((const int4*)src)[i];
        g_esrc[atomicAdd(&g_cur[d.x], 1)] = s.x;
        g_esrc[atomicAdd(&g_cur[d.y], 1)] = s.y;
        g_esrc[atomicAdd(&g_cur[d.z], 1)] = s.z;
        g_esrc[atomicAdd(&g_cur[d.w], 1)] = s.w;
    }
}

// ---------------- fused single-pass softmax + aggregation -------------------
__global__ __launch_bounds__(256) void aggregate_kernel(float* __restrict__ out) {
    int n = (blockIdx.x * blockDim.x + threadIdx.x) >> 5;
    int lane = threadIdx.x & 31;
    if (n >= N_NODES) return;
    int h = lane >> 3;
    int q = lane & 7;

    int begin = g_off[n];
    int end = g_off[n + 1];
    float erh = g_er[n * HEADS + h];

    float4 acc = make_float4(0.f, 0.f, 0.f, 0.f);
    float denom = 0.f;
    int i = begin;
    for (; i + 4 <= end; i += 4) {
        int s0 = g_esrc[i];
        int s1 = g_esrc[i + 1];
        int s2 = g_esrc[i + 2];
        int s3 = g_esrc[i + 3];
        float e0 = g_el[s0 * HEADS + h] + erh;
        float e1 = g_el[s1 * HEADS + h] + erh;
        float e2 = g_el[s2 * HEADS + h] + erh;
        float e3 = g_el[s3 * HEADS + h] + erh;
        e0 = e0 > 0.f ? e0 : NEG_SLOPE * e0;
        e1 = e1 > 0.f ? e1 : NEG_SLOPE * e1;
        e2 = e2 > 0.f ? e2 : NEG_SLOPE * e2;
        e3 = e3 > 0.f ? e3 : NEG_SLOPE * e3;
        float w0 = __expf(e0);
        float w1 = __expf(e1);
        float w2 = __expf(e2);
        float w3 = __expf(e3);
        float4 f0 = *(const float4*)&g_feat[(size_t)s0 * FEAT_DIM + lane * 4];
        float4 f1 = *(const float4*)&g_feat[(size_t)s1 * FEAT_DIM + lane * 4];
        float4 f2 = *(const float4*)&g_feat[(size_t)s2 * FEAT_DIM + lane * 4];
        float4 f3 = *(const float4*)&g_feat[(size_t)s3 * FEAT_DIM + lane * 4];
        denom += (w0 + w1) + (w2 + w3);
        acc.x += w0 * f0.x + w1 * f1.x + w2 * f2.x + w3 * f3.x;
        acc.y += w0 * f0.y + w1 * f1.y + w2 * f2.y + w3 * f3.y;
        acc.z += w0 * f0.z + w1 * f1.z + w2 * f2.z + w3 * f3.z;
        acc.w += w0 * f0.w + w1 * f1.w + w2 * f2.w + w3 * f3.w;
    }
    for (; i < end; i++) {
        int s0 = g_esrc[i];
        float e0 = g_el[s0 * HEADS + h] + erh;
        e0 = e0 > 0.f ? e0 : NEG_SLOPE * e0;
        float w0 = __expf(e0);
        float4 f0 = *(const float4*)&g_feat[(size_t)s0 * FEAT_DIM + lane * 4];
        denom += w0;
        acc.x += w0 * f0.x;
        acc.y += w0 * f0.y;
        acc.z += w0 * f0.z;
        acc.w += w0 * f0.w;
    }
    float inv = 0.25f / fmaxf(denom, 1e-9f);
    acc.x *= inv; acc.y *= inv; acc.z *= inv; acc.w *= inv;

#pragma unroll
    for (int o = 8; o <= 16; o <<= 1) {
        acc.x += __shfl_xor_sync(0xffffffffu, acc.x, o);
        acc.y += __shfl_xor_sync(0xffffffffu, acc.y, o);
        acc.z += __shfl_xor_sync(0xffffffffu, acc.z, o);
        acc.w += __shfl_xor_sync(0xffffffffu, acc.w, o);
    }
    if (lane < 8) {
        *(float4*)&out[(size_t)n * OUT_DIM + q * 4] = acc;
    }
}

// ---------------- launch ---------------------------------------------------
extern "C" void kernel_launch(void* const* d_in, const int* in_sizes, int n_in,
                              void* d_out, int out_size) {
    const float* x = (const float*)d_in[0];
    const float* W = (const float*)d_in[1];
    const float* attn_l = (const float*)d_in[2];
    const float* attn_r = (const float*)d_in[3];
    const int* src = (const int*)d_in[4];
    const int* dst = (const int*)d_in[5];
    float* out = (float*)d_out;

    static cudaStream_t s2 = nullptr;
    static cudaEvent_t evFork = nullptr, evJoin = nullptr;
    if (s2 == nullptr) {
        cudaStreamCreateWithFlags(&s2, cudaStreamNonBlocking);
        cudaEventCreateWithFlags(&evFork, cudaEventDisableTiming);
        cudaEventCreateWithFlags(&evJoin, cudaEventDisableTiming);
    }
    cudaFuncSetAttribute(gemm_mma_kernel, cudaFuncAttributeMaxDynamicSharedMemorySize, GEMM_SMEM);

    // fork: CSR build on s2, GEMM path on stream 0
    cudaEventRecord(evFork, 0);
    cudaStreamWaitEvent(s2, evFork, 0);

    wsplit_kernel<<<(IN_DIM * FEAT_DIM + 255) / 256, 256>>>(W);
    gemm_mma_kernel<<<(N_NODES + 127) / 128, 256, GEMM_SMEM>>>(x, attn_l, attn_r);

    zero_deg_kernel<<<(N_NODES / 4 + 255) / 256, 256, 0, s2>>>();
    hist_kernel<<<(N_EDGES / 4 + 255) / 256, 256, 0, s2>>>(dst);
    scan1_kernel<<<NB, SCAN_B, 0, s2>>>();
    scan2_kernel<<<1, 128, 0, s2>>>();
    scan3_kernel<<<(N_NODES + 255) / 256, 256, 0, s2>>>();
    scatter_kernel<<<(N_EDGES / 4 + 255) / 256, 256, 0, s2>>>(dst, src);

    // join: aggregate needs both branches
    cudaEventRecord(evJoin, s2);
    cudaStreamWaitEvent(0, evJoin, 0);
    aggregate_kernel<<<(N_NODES * 32 + 255) / 256, 256>>>(out);
}